// round 2
// baseline (speedup 1.0000x reference)
#include <cuda_runtime.h>
#include <math.h>
#include <math_constants.h>

// Problem constants (fixed shapes)
#define S_LEN 4096
#define HIDD  4096
#define NHEAD 32
#define NKVH  8
#define HDIM  128
#define NBLK  32   // S_LEN / 128

// ---------------------------------------------------------------------------
// Scratch (device globals — allocation inside kernel_launch is forbidden)
// ---------------------------------------------------------------------------
__device__ float g_q[S_LEN * NHEAD * HDIM];   // 64 MB
__device__ float g_k[S_LEN * NKVH * HDIM];    // 16 MB
__device__ float g_v[S_LEN * NKVH * HDIM];    // 16 MB
__device__ float g_ao[S_LEN * NHEAD * HDIM];  // 64 MB

// ---------------------------------------------------------------------------
// SGEMM: C[M,N] = A[M,K] @ B[K,N], all row-major, M,N multiples of 128,
// K multiple of 16. 256 threads, 128x128 tile, 8x8 per thread.
// Double-buffered smem: prefetch next K-tile into registers during compute.
// ---------------------------------------------------------------------------
__global__ __launch_bounds__(256) void sgemm_kernel(const float* __restrict__ A,
                                                    const float* __restrict__ B,
                                                    float* __restrict__ C,
                                                    int M, int N, int K) {
    __shared__ float As[2][16][132];  // transposed A tile, padded
    __shared__ float Bs[2][16][128];

    const int tid = threadIdx.x;
    const int tx  = tid & 15;
    const int ty  = tid >> 4;
    const int bxN = blockIdx.x * 128;
    const int byM = blockIdx.y * 128;

    const int aRow = tid >> 2;         // 0..63
    const int aCol = (tid & 3) << 2;   // 0,4,8,12
    const int bRow = tid >> 5;         // 0..7
    const int bCol = (tid & 31) << 2;  // 0..124

    float acc[8][8];
#pragma unroll
    for (int i = 0; i < 8; i++)
#pragma unroll
        for (int j = 0; j < 8; j++) acc[i][j] = 0.f;

    // Initial tile -> buffer 0
#pragma unroll
    for (int i = 0; i < 2; i++) {
        float4 v = *(const float4*)&A[(size_t)(byM + aRow + i * 64) * K + aCol];
        As[0][aCol + 0][aRow + i * 64] = v.x;
        As[0][aCol + 1][aRow + i * 64] = v.y;
        As[0][aCol + 2][aRow + i * 64] = v.z;
        As[0][aCol + 3][aRow + i * 64] = v.w;
    }
#pragma unroll
    for (int i = 0; i < 2; i++) {
        *(float4*)&Bs[0][bRow + i * 8][bCol] =
            *(const float4*)&B[(size_t)(bRow + i * 8) * N + bxN + bCol];
    }
    __syncthreads();

    int buf = 0;
    for (int kt = 0; kt < K; kt += 16) {
        const int nxt = kt + 16;
        float4 pa[2], pb[2];
        if (nxt < K) {
#pragma unroll
            for (int i = 0; i < 2; i++)
                pa[i] = *(const float4*)&A[(size_t)(byM + aRow + i * 64) * K + nxt + aCol];
#pragma unroll
            for (int i = 0; i < 2; i++)
                pb[i] = *(const float4*)&B[(size_t)(nxt + bRow + i * 8) * N + bxN + bCol];
        }

#pragma unroll
        for (int kk = 0; kk < 16; kk++) {
            float4 a0 = *(float4*)&As[buf][kk][ty * 8];
            float4 a1 = *(float4*)&As[buf][kk][ty * 8 + 4];
            float4 b0 = *(float4*)&Bs[buf][kk][tx * 8];
            float4 b1 = *(float4*)&Bs[buf][kk][tx * 8 + 4];
            float ra[8] = {a0.x, a0.y, a0.z, a0.w, a1.x, a1.y, a1.z, a1.w};
            float rb[8] = {b0.x, b0.y, b0.z, b0.w, b1.x, b1.y, b1.z, b1.w};
#pragma unroll
            for (int ii = 0; ii < 8; ii++)
#pragma unroll
                for (int jj = 0; jj < 8; jj++)
                    acc[ii][jj] = fmaf(ra[ii], rb[jj], acc[ii][jj]);
        }

        if (nxt < K) {
            const int nb = buf ^ 1;
#pragma unroll
            for (int i = 0; i < 2; i++) {
                As[nb][aCol + 0][aRow + i * 64] = pa[i].x;
                As[nb][aCol + 1][aRow + i * 64] = pa[i].y;
                As[nb][aCol + 2][aRow + i * 64] = pa[i].z;
                As[nb][aCol + 3][aRow + i * 64] = pa[i].w;
            }
#pragma unroll
            for (int i = 0; i < 2; i++)
                *(float4*)&Bs[nb][bRow + i * 8][bCol] = pb[i];
        }
        __syncthreads();
        buf ^= 1;
    }

#pragma unroll
    for (int ii = 0; ii < 8; ii++) {
        float4 o0 = make_float4(acc[ii][0], acc[ii][1], acc[ii][2], acc[ii][3]);
        float4 o1 = make_float4(acc[ii][4], acc[ii][5], acc[ii][6], acc[ii][7]);
        size_t off = (size_t)(byM + ty * 8 + ii) * N + bxN + tx * 8;
        *(float4*)&C[off]     = o0;
        *(float4*)&C[off + 4] = o1;
    }
}

// ---------------------------------------------------------------------------
// RoPE (in-place). X: [S, nheads, 128]. Pair (p, p+64). Optional scale folded.
// Angles: fp32-rounded inv_freq and argument (to match the jax fp32 chain),
// then double-precision sincos so accuracy is independent of fast-math flags.
// ---------------------------------------------------------------------------
__global__ void rope_kernel(float* __restrict__ X, int nheads, float scale) {
    int idx = blockIdx.x * blockDim.x + threadIdx.x;
    int total = S_LEN * nheads * 64;
    if (idx >= total) return;
    int p    = idx & 63;
    int th   = idx >> 6;
    int head = th % nheads;
    int s    = th / nheads;

    float invf = (float)exp(-(double)p * (1.0 / 64.0) * log(10000.0));
    float ff   = (float)s * invf;  // fp32 rounding, as in the reference
    double cd, sd;
    sincos((double)ff, &sd, &cd);
    float c  = (float)cd;
    float sn = (float)sd;

    size_t base = ((size_t)s * nheads + head) * HDIM;
    float x1 = X[base + p];
    float x2 = X[base + p + 64];
    X[base + p]      = (x1 * c - x2 * sn) * scale;
    X[base + p + 64] = (x2 * c + x1 * sn) * scale;
}

// ---------------------------------------------------------------------------
// Block-sparse flash attention.
// Grid: (q_block 0..31, head 0..31). 256 threads = 16x16, 8x8 per thread.
// Attended kv blocks for q-block i: {0} then {max(1,i-7) .. i}.
// Causal triangular mask only needed when j == i.
// Dynamic smem: Q(64K) + K/P(64K) + V(64K) + 2 reduce bufs(16K) = 208 KB.
// ---------------------------------------------------------------------------
#define ATT_SMEM_FLOATS (16384 * 3 + 2048 * 2)

__global__ __launch_bounds__(256, 1) void attn_kernel(const float* __restrict__ Q,
                                                      const float* __restrict__ K,
                                                      const float* __restrict__ V,
                                                      float* __restrict__ AO) {
    extern __shared__ float sm[];
    float* sQ   = sm;            // [128][128]
    float* sKP  = sm + 16384;    // K (swizzled) then P (plain)
    float* sV   = sm + 32768;    // [128][128]
    float* redm = sm + 49152;    // [128][16]
    float* reds = sm + 51200;    // [128][16]

    const int iq  = blockIdx.x;
    const int h   = blockIdx.y;
    const int kvh = h >> 2;      // n_rep = 4
    const int tid = threadIdx.x;
    const int tx  = tid & 15;
    const int ty  = tid >> 4;

    // Load Q tile (already RoPE'd and pre-scaled by 1/sqrt(D))
    for (int idx = tid; idx < 128 * 32; idx += 256) {
        int r  = idx >> 5;
        int c4 = (idx & 31) << 2;
        *(float4*)&sQ[r * 128 + c4] =
            *(const float4*)&Q[(size_t)(iq * 128 + r) * (NHEAD * HDIM) + h * HDIM + c4];
    }

    float m_i[8], l_i[8], oacc[8][8];
#pragma unroll
    for (int ii = 0; ii < 8; ii++) {
        m_i[ii] = -CUDART_INF_F;
        l_i[ii] = 0.f;
#pragma unroll
        for (int jj = 0; jj < 8; jj++) oacc[ii][jj] = 0.f;
    }

    const int jlo = (iq - 7 < 1) ? 1 : (iq - 7);
    const int nbl = (iq == 0) ? 1 : (iq - jlo + 2);

    for (int b = 0; b < nbl; b++) {
        const int j = (b == 0) ? 0 : (jlo + b - 1);

        __syncthreads();  // prior PV reads done (and Q visible on first iter)
        for (int idx = tid; idx < 128 * 32; idx += 256) {
            int r  = idx >> 5;
            int c4 = idx & 31;
            size_t goff = (size_t)(j * 128 + r) * (NKVH * HDIM) + kvh * HDIM + (c4 << 2);
            int sw = (c4 ^ ((r >> 3) & 7)) << 2;  // XOR swizzle: conflict-free K reads
            *(float4*)&sKP[r * 128 + sw]        = *(const float4*)&K[goff];
            *(float4*)&sV[r * 128 + (c4 << 2)]  = *(const float4*)&V[goff];
        }
        __syncthreads();

        // S = Q @ K^T  (128x128, per-thread 8x8)
        float sreg[8][8];
#pragma unroll
        for (int ii = 0; ii < 8; ii++)
#pragma unroll
            for (int jj = 0; jj < 8; jj++) sreg[ii][jj] = 0.f;

        for (int d4 = 0; d4 < 32; d4++) {
            float4 qv[8], kv[8];
#pragma unroll
            for (int ii = 0; ii < 8; ii++)
                qv[ii] = *(float4*)&sQ[(ty * 8 + ii) * 128 + (d4 << 2)];
#pragma unroll
            for (int jj = 0; jj < 8; jj++)
                kv[jj] = *(float4*)&sKP[(tx * 8 + jj) * 128 + ((d4 ^ (tx & 7)) << 2)];
#pragma unroll
            for (int ii = 0; ii < 8; ii++)
#pragma unroll
                for (int jj = 0; jj < 8; jj++) {
                    sreg[ii][jj] = fmaf(qv[ii].x, kv[jj].x, sreg[ii][jj]);
                    sreg[ii][jj] = fmaf(qv[ii].y, kv[jj].y, sreg[ii][jj]);
                    sreg[ii][jj] = fmaf(qv[ii].z, kv[jj].z, sreg[ii][jj]);
                    sreg[ii][jj] = fmaf(qv[ii].w, kv[jj].w, sreg[ii][jj]);
                }
        }

        if (j == iq) {  // causal triangle within the diagonal block
#pragma unroll
            for (int ii = 0; ii < 8; ii++)
#pragma unroll
                for (int jj = 0; jj < 8; jj++)
                    if (tx * 8 + jj > ty * 8 + ii) sreg[ii][jj] = -CUDART_INF_F;
        }

        // Row max across the 16 tx threads
#pragma unroll
        for (int ii = 0; ii < 8; ii++) {
            float lm = sreg[ii][0];
#pragma unroll
            for (int jj = 1; jj < 8; jj++) lm = fmaxf(lm, sreg[ii][jj]);
            redm[(ty * 8 + ii) * 16 + tx] = lm;
        }
        __syncthreads();  // barrier A: all S computed; K reads finished

        float mnew[8], scl[8];
#pragma unroll
        for (int ii = 0; ii < 8; ii++) {
            float m = m_i[ii];
#pragma unroll
            for (int t = 0; t < 16; t++) m = fmaxf(m, redm[(ty * 8 + ii) * 16 + t]);
            mnew[ii] = m;
            scl[ii]  = expf(m_i[ii] - m);
            m_i[ii]  = m;
        }

        // P = exp(S - mnew); partial row sums; write P over K; rescale O
#pragma unroll
        for (int ii = 0; ii < 8; ii++) {
            float ps = 0.f;
#pragma unroll
            for (int jj = 0; jj < 8; jj++) {
                float p = expf(sreg[ii][jj] - mnew[ii]);
                sreg[ii][jj] = p;
                ps += p;
            }
            reds[(ty * 8 + ii) * 16 + tx] = ps;
#pragma unroll
            for (int jj = 0; jj < 8; jj++) oacc[ii][jj] *= scl[ii];
            float4 p0 = make_float4(sreg[ii][0], sreg[ii][1], sreg[ii][2], sreg[ii][3]);
            float4 p1 = make_float4(sreg[ii][4], sreg[ii][5], sreg[ii][6], sreg[ii][7]);
            *(float4*)&sKP[(ty * 8 + ii) * 128 + tx * 8]     = p0;
            *(float4*)&sKP[(ty * 8 + ii) * 128 + tx * 8 + 4] = p1;
        }
        __syncthreads();  // barrier B: P + reds visible

#pragma unroll
        for (int ii = 0; ii < 8; ii++) {
            float rs = 0.f;
#pragma unroll
            for (int t = 0; t < 16; t++) rs += reds[(ty * 8 + ii) * 16 + t];
            l_i[ii] = l_i[ii] * scl[ii] + rs;
        }

        // O += P @ V
        for (int c = 0; c < 128; c++) {
            float4 v0 = *(float4*)&sV[c * 128 + tx * 8];
            float4 v1 = *(float4*)&sV[c * 128 + tx * 8 + 4];
            float pr[8];
#pragma unroll
            for (int ii = 0; ii < 8; ii++) pr[ii] = sKP[(ty * 8 + ii) * 128 + c];
#pragma unroll
            for (int ii = 0; ii < 8; ii++) {
                oacc[ii][0] = fmaf(pr[ii], v0.x, oacc[ii][0]);
                oacc[ii][1] = fmaf(pr[ii], v0.y, oacc[ii][1]);
                oacc[ii][2] = fmaf(pr[ii], v0.z, oacc[ii][2]);
                oacc[ii][3] = fmaf(pr[ii], v0.w, oacc[ii][3]);
                oacc[ii][4] = fmaf(pr[ii], v1.x, oacc[ii][4]);
                oacc[ii][5] = fmaf(pr[ii], v1.y, oacc[ii][5]);
                oacc[ii][6] = fmaf(pr[ii], v1.z, oacc[ii][6]);
                oacc[ii][7] = fmaf(pr[ii], v1.w, oacc[ii][7]);
            }
        }
    }

    // Epilogue: O / l, write [S, NH*D]
#pragma unroll
    for (int ii = 0; ii < 8; ii++) {
        float inv = 1.0f / l_i[ii];
        float4 o0 = make_float4(oacc[ii][0] * inv, oacc[ii][1] * inv,
                                oacc[ii][2] * inv, oacc[ii][3] * inv);
        float4 o1 = make_float4(oacc[ii][4] * inv, oacc[ii][5] * inv,
                                oacc[ii][6] * inv, oacc[ii][7] * inv);
        size_t off = (size_t)(iq * 128 + ty * 8 + ii) * (NHEAD * HDIM) + h * HDIM + tx * 8;
        *(float4*)&AO[off]     = o0;
        *(float4*)&AO[off + 4] = o1;
    }
}

// ---------------------------------------------------------------------------
// kernel_launch
// ---------------------------------------------------------------------------
extern "C" void kernel_launch(void* const* d_in, const int* in_sizes, int n_in,
                              void* d_out, int out_size) {
    const float* hs = (const float*)d_in[0];
    const float* wq = (const float*)d_in[1];
    const float* wk = (const float*)d_in[2];
    const float* wv = (const float*)d_in[3];
    const float* wo = (const float*)d_in[4];
    float* out = (float*)d_out;

    float *q, *k, *v, *ao;
    cudaGetSymbolAddress((void**)&q,  g_q);
    cudaGetSymbolAddress((void**)&k,  g_k);
    cudaGetSymbolAddress((void**)&v,  g_v);
    cudaGetSymbolAddress((void**)&ao, g_ao);

    const int att_smem = ATT_SMEM_FLOATS * (int)sizeof(float);  // 212992 B
    cudaFuncSetAttribute(attn_kernel, cudaFuncAttributeMaxDynamicSharedMemorySize, att_smem);

    dim3 blk(256);
    // QKV projections
    sgemm_kernel<<<dim3(32, 32), blk>>>(hs, wq, q, S_LEN, NHEAD * HDIM, HIDD);
    sgemm_kernel<<<dim3(8, 32),  blk>>>(hs, wk, k, S_LEN, NKVH * HDIM, HIDD);
    sgemm_kernel<<<dim3(8, 32),  blk>>>(hs, wv, v, S_LEN, NKVH * HDIM, HIDD);
    // RoPE (Q pre-scaled by 1/sqrt(128))
    rope_kernel<<<(S_LEN * NHEAD * 64 + 255) / 256, 256>>>(q, NHEAD, 0.08838834764831845f);
    rope_kernel<<<(S_LEN * NKVH * 64 + 255) / 256, 256>>>(k, NKVH, 1.0f);
    // Block-sparse flash attention
    attn_kernel<<<dim3(NBLK, NHEAD), blk, att_smem>>>(q, k, v, ao);
    // Output projection
    sgemm_kernel<<<dim3(32, 32), blk>>>(ao, wo, out, S_LEN, HIDD, NHEAD * HDIM);
}

// round 5
// speedup vs baseline: 2.1676x; 2.1676x over previous
#include <cuda_runtime.h>
#include <math.h>
#include <math_constants.h>
#include <stdint.h>

// Problem constants (fixed shapes)
#define S_LEN 4096
#define HIDD  4096
#define NHEAD 32
#define NKVH  8
#define HDIM  128
#define NBLK  32   // S_LEN / 128

// ---------------------------------------------------------------------------
// Scratch (device globals — allocation inside kernel_launch is forbidden)
// ---------------------------------------------------------------------------
__device__ float g_q[S_LEN * NHEAD * HDIM];   // 64 MB
__device__ float g_k[S_LEN * NKVH * HDIM];    // 16 MB
__device__ float g_v[S_LEN * NKVH * HDIM];    // 16 MB
__device__ float g_ao[S_LEN * NHEAD * HDIM];  // 64 MB

// ---------------------------------------------------------------------------
// TF32 tensor-core GEMM: C[M,N] = A[M,K] @ B[K,N], row-major.
// M,N multiples of 128, K multiple of 16.
// 256 threads = 8 warps (2x4), warp tile 64x32, mma.m16n8k8 tf32, fp32 accum.
// Smem: K-major [16][136] for A (transposed) and B; stride 136 => fragment
// LDS are bank-conflict-free (bank = t*8+g covers 0..31 exactly).
// ---------------------------------------------------------------------------
#define SAB_STRIDE 136

__device__ __forceinline__ uint32_t f2tf32(float f) {
    uint32_t u;
    asm("cvt.rna.tf32.f32 %0, %1;" : "=r"(u) : "f"(f));
    return u;
}

__device__ __forceinline__ void mma_tf32(float* c, const uint32_t* a, const uint32_t* b) {
    asm volatile(
        "mma.sync.aligned.m16n8k8.row.col.f32.tf32.tf32.f32 "
        "{%0,%1,%2,%3}, {%4,%5,%6,%7}, {%8,%9}, {%0,%1,%2,%3};"
        : "+f"(c[0]), "+f"(c[1]), "+f"(c[2]), "+f"(c[3])
        : "r"(a[0]), "r"(a[1]), "r"(a[2]), "r"(a[3]), "r"(b[0]), "r"(b[1]));
}

__global__ __launch_bounds__(256) void tgemm_kernel(const float* __restrict__ A,
                                                    const float* __restrict__ B,
                                                    float* __restrict__ C,
                                                    int M, int N, int K) {
    __shared__ uint32_t sA[2][16 * SAB_STRIDE];  // [k][m] transposed
    __shared__ uint32_t sB[2][16 * SAB_STRIDE];  // [k][n]

    const int tid  = threadIdx.x;
    const int lane = tid & 31;
    const int wid  = tid >> 5;
    const int g    = lane >> 2;   // group id 0..7
    const int t    = lane & 3;    // thread-in-group 0..3
    const int wm   = wid >> 2;    // 0..1
    const int wn   = wid & 3;     // 0..3

    const int bxN = blockIdx.x * 128;
    const int byM = blockIdx.y * 128;

    const int aRow = tid >> 2;         // 0..63
    const int aCol = (tid & 3) << 2;   // 0,4,8,12
    const int bRow = tid >> 5;         // 0..7
    const int bCol = (tid & 31) << 2;  // 0..124

    float acc[4][4][4];
#pragma unroll
    for (int i = 0; i < 4; i++)
#pragma unroll
        for (int j = 0; j < 4; j++)
#pragma unroll
            for (int c = 0; c < 4; c++) acc[i][j][c] = 0.f;

    // ---- initial tile -> buffer 0 ----
#pragma unroll
    for (int i = 0; i < 2; i++) {
        float4 v = *(const float4*)&A[(size_t)(byM + aRow + i * 64) * K + aCol];
        int m = aRow + i * 64;
        sA[0][(aCol + 0) * SAB_STRIDE + m] = f2tf32(v.x);
        sA[0][(aCol + 1) * SAB_STRIDE + m] = f2tf32(v.y);
        sA[0][(aCol + 2) * SAB_STRIDE + m] = f2tf32(v.z);
        sA[0][(aCol + 3) * SAB_STRIDE + m] = f2tf32(v.w);
    }
#pragma unroll
    for (int i = 0; i < 2; i++) {
        float4 v = *(const float4*)&B[(size_t)(bRow + i * 8) * N + bxN + bCol];
        uint4 u = make_uint4(f2tf32(v.x), f2tf32(v.y), f2tf32(v.z), f2tf32(v.w));
        *(uint4*)&sB[0][(bRow + i * 8) * SAB_STRIDE + bCol] = u;
    }
    __syncthreads();

    int buf = 0;
    for (int kt = 0; kt < K; kt += 16) {
        const int nxt = kt + 16;
        float4 pa[2], pb[2];
        if (nxt < K) {
#pragma unroll
            for (int i = 0; i < 2; i++)
                pa[i] = *(const float4*)&A[(size_t)(byM + aRow + i * 64) * K + nxt + aCol];
#pragma unroll
            for (int i = 0; i < 2; i++)
                pb[i] = *(const float4*)&B[(size_t)(nxt + bRow + i * 8) * N + bxN + bCol];
        }

        // ---- compute: two k-chunks of 8 ----
#pragma unroll
        for (int kc = 0; kc < 2; kc++) {
            const int k0 = kc * 8 + t;
            uint32_t afr[4][4], bfr[4][2];
#pragma unroll
            for (int mi = 0; mi < 4; mi++) {
                int mr = wm * 64 + mi * 16 + g;
                afr[mi][0] = sA[buf][k0 * SAB_STRIDE + mr];
                afr[mi][1] = sA[buf][k0 * SAB_STRIDE + mr + 8];
                afr[mi][2] = sA[buf][(k0 + 4) * SAB_STRIDE + mr];
                afr[mi][3] = sA[buf][(k0 + 4) * SAB_STRIDE + mr + 8];
            }
#pragma unroll
            for (int ni = 0; ni < 4; ni++) {
                int nb = wn * 32 + ni * 8 + g;
                bfr[ni][0] = sB[buf][k0 * SAB_STRIDE + nb];
                bfr[ni][1] = sB[buf][(k0 + 4) * SAB_STRIDE + nb];
            }
#pragma unroll
            for (int mi = 0; mi < 4; mi++)
#pragma unroll
                for (int ni = 0; ni < 4; ni++)
                    mma_tf32(acc[mi][ni], afr[mi], bfr[ni]);
        }

        if (nxt < K) {
            const int nb = buf ^ 1;
#pragma unroll
            for (int i = 0; i < 2; i++) {
                int m = aRow + i * 64;
                sA[nb][(aCol + 0) * SAB_STRIDE + m] = f2tf32(pa[i].x);
                sA[nb][(aCol + 1) * SAB_STRIDE + m] = f2tf32(pa[i].y);
                sA[nb][(aCol + 2) * SAB_STRIDE + m] = f2tf32(pa[i].z);
                sA[nb][(aCol + 3) * SAB_STRIDE + m] = f2tf32(pa[i].w);
            }
#pragma unroll
            for (int i = 0; i < 2; i++) {
                uint4 u = make_uint4(f2tf32(pb[i].x), f2tf32(pb[i].y),
                                     f2tf32(pb[i].z), f2tf32(pb[i].w));
                *(uint4*)&sB[nb][(bRow + i * 8) * SAB_STRIDE + bCol] = u;
            }
        }
        __syncthreads();
        buf ^= 1;
    }

    // ---- epilogue ----
#pragma unroll
    for (int mi = 0; mi < 4; mi++) {
#pragma unroll
        for (int ni = 0; ni < 4; ni++) {
            int row = byM + wm * 64 + mi * 16 + g;
            int col = bxN + wn * 32 + ni * 8 + 2 * t;
            *(float2*)&C[(size_t)row * N + col]       = make_float2(acc[mi][ni][0], acc[mi][ni][1]);
            *(float2*)&C[(size_t)(row + 8) * N + col] = make_float2(acc[mi][ni][2], acc[mi][ni][3]);
        }
    }
}

// ---------------------------------------------------------------------------
// RoPE (in-place). X: [S, nheads, 128]. Pair (p, p+64). Optional scale folded.
// ---------------------------------------------------------------------------
__global__ void rope_kernel(float* __restrict__ X, int nheads, float scale) {
    int idx = blockIdx.x * blockDim.x + threadIdx.x;
    int total = S_LEN * nheads * 64;
    if (idx >= total) return;
    int p    = idx & 63;
    int th   = idx >> 6;
    int head = th % nheads;
    int s    = th / nheads;

    float invf = (float)exp(-(double)p * (1.0 / 64.0) * log(10000.0));
    float ff   = (float)s * invf;  // fp32 rounding, as in the reference
    double cd, sd;
    sincos((double)ff, &sd, &cd);
    float c  = (float)cd;
    float sn = (float)sd;

    size_t base = ((size_t)s * nheads + head) * HDIM;
    float x1 = X[base + p];
    float x2 = X[base + p + 64];
    X[base + p]      = (x1 * c - x2 * sn) * scale;
    X[base + p + 64] = (x2 * c + x1 * sn) * scale;
}

// ---------------------------------------------------------------------------
// Block-sparse flash attention (fp32 SIMT), unchanged from the passing R2.
// ---------------------------------------------------------------------------
#define ATT_SMEM_FLOATS (16384 * 3 + 2048 * 2)

__global__ __launch_bounds__(256, 1) void attn_kernel(const float* __restrict__ Q,
                                                      const float* __restrict__ K,
                                                      const float* __restrict__ V,
                                                      float* __restrict__ AO) {
    extern __shared__ float sm[];
    float* sQ   = sm;            // [128][128]
    float* sKP  = sm + 16384;    // K (swizzled) then P (plain)
    float* sV   = sm + 32768;    // [128][128]
    float* redm = sm + 49152;    // [128][16]
    float* reds = sm + 51200;    // [128][16]

    const int iq  = blockIdx.x;
    const int h   = blockIdx.y;
    const int kvh = h >> 2;      // n_rep = 4
    const int tid = threadIdx.x;
    const int tx  = tid & 15;
    const int ty  = tid >> 4;

    for (int idx = tid; idx < 128 * 32; idx += 256) {
        int r  = idx >> 5;
        int c4 = (idx & 31) << 2;
        *(float4*)&sQ[r * 128 + c4] =
            *(const float4*)&Q[(size_t)(iq * 128 + r) * (NHEAD * HDIM) + h * HDIM + c4];
    }

    float m_i[8], l_i[8], oacc[8][8];
#pragma unroll
    for (int ii = 0; ii < 8; ii++) {
        m_i[ii] = -CUDART_INF_F;
        l_i[ii] = 0.f;
#pragma unroll
        for (int jj = 0; jj < 8; jj++) oacc[ii][jj] = 0.f;
    }

    const int jlo = (iq - 7 < 1) ? 1 : (iq - 7);
    const int nbl = (iq == 0) ? 1 : (iq - jlo + 2);

    for (int b = 0; b < nbl; b++) {
        const int j = (b == 0) ? 0 : (jlo + b - 1);

        __syncthreads();
        for (int idx = tid; idx < 128 * 32; idx += 256) {
            int r  = idx >> 5;
            int c4 = idx & 31;
            size_t goff = (size_t)(j * 128 + r) * (NKVH * HDIM) + kvh * HDIM + (c4 << 2);
            int sw = (c4 ^ ((r >> 3) & 7)) << 2;
            *(float4*)&sKP[r * 128 + sw]        = *(const float4*)&K[goff];
            *(float4*)&sV[r * 128 + (c4 << 2)]  = *(const float4*)&V[goff];
        }
        __syncthreads();

        float sreg[8][8];
#pragma unroll
        for (int ii = 0; ii < 8; ii++)
#pragma unroll
            for (int jj = 0; jj < 8; jj++) sreg[ii][jj] = 0.f;

        for (int d4 = 0; d4 < 32; d4++) {
            float4 qv[8], kv[8];
#pragma unroll
            for (int ii = 0; ii < 8; ii++)
                qv[ii] = *(float4*)&sQ[(ty * 8 + ii) * 128 + (d4 << 2)];
#pragma unroll
            for (int jj = 0; jj < 8; jj++)
                kv[jj] = *(float4*)&sKP[(tx * 8 + jj) * 128 + ((d4 ^ (tx & 7)) << 2)];
#pragma unroll
            for (int ii = 0; ii < 8; ii++)
#pragma unroll
                for (int jj = 0; jj < 8; jj++) {
                    sreg[ii][jj] = fmaf(qv[ii].x, kv[jj].x, sreg[ii][jj]);
                    sreg[ii][jj] = fmaf(qv[ii].y, kv[jj].y, sreg[ii][jj]);
                    sreg[ii][jj] = fmaf(qv[ii].z, kv[jj].z, sreg[ii][jj]);
                    sreg[ii][jj] = fmaf(qv[ii].w, kv[jj].w, sreg[ii][jj]);
                }
        }

        if (j == iq) {
#pragma unroll
            for (int ii = 0; ii < 8; ii++)
#pragma unroll
                for (int jj = 0; jj < 8; jj++)
                    if (tx * 8 + jj > ty * 8 + ii) sreg[ii][jj] = -CUDART_INF_F;
        }

#pragma unroll
        for (int ii = 0; ii < 8; ii++) {
            float lm = sreg[ii][0];
#pragma unroll
            for (int jj = 1; jj < 8; jj++) lm = fmaxf(lm, sreg[ii][jj]);
            redm[(ty * 8 + ii) * 16 + tx] = lm;
        }
        __syncthreads();

        float mnew[8], scl[8];
#pragma unroll
        for (int ii = 0; ii < 8; ii++) {
            float m = m_i[ii];
#pragma unroll
            for (int tt = 0; tt < 16; tt++) m = fmaxf(m, redm[(ty * 8 + ii) * 16 + tt]);
            mnew[ii] = m;
            scl[ii]  = expf(m_i[ii] - m);
            m_i[ii]  = m;
        }

#pragma unroll
        for (int ii = 0; ii < 8; ii++) {
            float ps = 0.f;
#pragma unroll
            for (int jj = 0; jj < 8; jj++) {
                float p = expf(sreg[ii][jj] - mnew[ii]);
                sreg[ii][jj] = p;
                ps += p;
            }
            reds[(ty * 8 + ii) * 16 + tx] = ps;
#pragma unroll
            for (int jj = 0; jj < 8; jj++) oacc[ii][jj] *= scl[ii];
            float4 p0 = make_float4(sreg[ii][0], sreg[ii][1], sreg[ii][2], sreg[ii][3]);
            float4 p1 = make_float4(sreg[ii][4], sreg[ii][5], sreg[ii][6], sreg[ii][7]);
            *(float4*)&sKP[(ty * 8 + ii) * 128 + tx * 8]     = p0;
            *(float4*)&sKP[(ty * 8 + ii) * 128 + tx * 8 + 4] = p1;
        }
        __syncthreads();

#pragma unroll
        for (int ii = 0; ii < 8; ii++) {
            float rs = 0.f;
#pragma unroll
            for (int tt = 0; tt < 16; tt++) rs += reds[(ty * 8 + ii) * 16 + tt];
            l_i[ii] = l_i[ii] * scl[ii] + rs;
        }

        for (int c = 0; c < 128; c++) {
            float4 v0 = *(float4*)&sV[c * 128 + tx * 8];
            float4 v1 = *(float4*)&sV[c * 128 + tx * 8 + 4];
            float pr[8];
#pragma unroll
            for (int ii = 0; ii < 8; ii++) pr[ii] = sKP[(ty * 8 + ii) * 128 + c];
#pragma unroll
            for (int ii = 0; ii < 8; ii++) {
                oacc[ii][0] = fmaf(pr[ii], v0.x, oacc[ii][0]);
                oacc[ii][1] = fmaf(pr[ii], v0.y, oacc[ii][1]);
                oacc[ii][2] = fmaf(pr[ii], v0.z, oacc[ii][2]);
                oacc[ii][3] = fmaf(pr[ii], v0.w, oacc[ii][3]);
                oacc[ii][4] = fmaf(pr[ii], v1.x, oacc[ii][4]);
                oacc[ii][5] = fmaf(pr[ii], v1.y, oacc[ii][5]);
                oacc[ii][6] = fmaf(pr[ii], v1.z, oacc[ii][6]);
                oacc[ii][7] = fmaf(pr[ii], v1.w, oacc[ii][7]);
            }
        }
    }

#pragma unroll
    for (int ii = 0; ii < 8; ii++) {
        float inv = 1.0f / l_i[ii];
        float4 o0 = make_float4(oacc[ii][0] * inv, oacc[ii][1] * inv,
                                oacc[ii][2] * inv, oacc[ii][3] * inv);
        float4 o1 = make_float4(oacc[ii][4] * inv, oacc[ii][5] * inv,
                                oacc[ii][6] * inv, oacc[ii][7] * inv);
        size_t off = (size_t)(iq * 128 + ty * 8 + ii) * (NHEAD * HDIM) + h * HDIM + tx * 8;
        *(float4*)&AO[off]     = o0;
        *(float4*)&AO[off + 4] = o1;
    }
}

// ---------------------------------------------------------------------------
// kernel_launch
// ---------------------------------------------------------------------------
extern "C" void kernel_launch(void* const* d_in, const int* in_sizes, int n_in,
                              void* d_out, int out_size) {
    const float* hs = (const float*)d_in[0];
    const float* wq = (const float*)d_in[1];
    const float* wk = (const float*)d_in[2];
    const float* wv = (const float*)d_in[3];
    const float* wo = (const float*)d_in[4];
    float* out = (float*)d_out;

    float *q, *k, *v, *ao;
    cudaGetSymbolAddress((void**)&q,  g_q);
    cudaGetSymbolAddress((void**)&k,  g_k);
    cudaGetSymbolAddress((void**)&v,  g_v);
    cudaGetSymbolAddress((void**)&ao, g_ao);

    const int att_smem = ATT_SMEM_FLOATS * (int)sizeof(float);  // 212992 B
    cudaFuncSetAttribute(attn_kernel, cudaFuncAttributeMaxDynamicSharedMemorySize, att_smem);

    dim3 blk(256);
    // QKV projections (tf32 tensor cores)
    tgemm_kernel<<<dim3(32, 32), blk>>>(hs, wq, q, S_LEN, NHEAD * HDIM, HIDD);
    tgemm_kernel<<<dim3(8, 32),  blk>>>(hs, wk, k, S_LEN, NKVH * HDIM, HIDD);
    tgemm_kernel<<<dim3(8, 32),  blk>>>(hs, wv, v, S_LEN, NKVH * HDIM, HIDD);
    // RoPE (Q pre-scaled by 1/sqrt(128))
    rope_kernel<<<(S_LEN * NHEAD * 64 + 255) / 256, 256>>>(q, NHEAD, 0.08838834764831845f);
    rope_kernel<<<(S_LEN * NKVH * 64 + 255) / 256, 256>>>(k, NKVH, 1.0f);
    // Block-sparse flash attention (fp32)
    attn_kernel<<<dim3(NBLK, NHEAD), blk, att_smem>>>(q, k, v, ao);
    // Output projection (tf32 tensor cores)
    tgemm_kernel<<<dim3(32, 32), blk>>>(ao, wo, out, S_LEN, HIDD, NHEAD * HDIM);
}

// round 7
// speedup vs baseline: 2.4606x; 1.1352x over previous
#include <cuda_runtime.h>
#include <math.h>
#include <math_constants.h>
#include <stdint.h>

// Problem constants (fixed shapes)
#define S_LEN 4096
#define HIDD  4096
#define NHEAD 32
#define NKVH  8
#define HDIM  128
#define NBLK  32   // S_LEN / 128

// ---------------------------------------------------------------------------
// Scratch (device globals — allocation inside kernel_launch is forbidden)
// ---------------------------------------------------------------------------
__device__ float g_q[S_LEN * NHEAD * HDIM];   // 64 MB
__device__ float g_k[S_LEN * NKVH * HDIM];    // 16 MB
__device__ float g_v[S_LEN * NKVH * HDIM];    // 16 MB
__device__ float g_ao[S_LEN * NHEAD * HDIM];  // 64 MB

// ---------------------------------------------------------------------------
// mma helpers
// ---------------------------------------------------------------------------
__device__ __forceinline__ uint32_t f2tf32(float f) {
    uint32_t u;
    asm("cvt.rna.tf32.f32 %0, %1;" : "=r"(u) : "f"(f));
    return u;
}

// 3xTF32 split: f = hi + lo to ~22 mantissa bits
__device__ __forceinline__ void split_tf32(float f, uint32_t& hi, uint32_t& lo) {
    hi = f2tf32(f);
    lo = f2tf32(f - __uint_as_float(hi));
}

__device__ __forceinline__ void mma_tf32(float* c, const uint32_t* a, const uint32_t* b) {
    asm volatile(
        "mma.sync.aligned.m16n8k8.row.col.f32.tf32.tf32.f32 "
        "{%0,%1,%2,%3}, {%4,%5,%6,%7}, {%8,%9}, {%0,%1,%2,%3};"
        : "+f"(c[0]), "+f"(c[1]), "+f"(c[2]), "+f"(c[3])
        : "r"(a[0]), "r"(a[1]), "r"(a[2]), "r"(a[3]), "r"(b[0]), "r"(b[1]));
}

// ---------------------------------------------------------------------------
// TF32 tensor-core GEMM (unchanged from R5 passing kernel).
// ---------------------------------------------------------------------------
#define SAB_STRIDE 136

__global__ __launch_bounds__(256) void tgemm_kernel(const float* __restrict__ A,
                                                    const float* __restrict__ B,
                                                    float* __restrict__ C,
                                                    int M, int N, int K) {
    __shared__ uint32_t sA[2][16 * SAB_STRIDE];  // [k][m] transposed
    __shared__ uint32_t sB[2][16 * SAB_STRIDE];  // [k][n]

    const int tid  = threadIdx.x;
    const int lane = tid & 31;
    const int wid  = tid >> 5;
    const int g    = lane >> 2;
    const int t    = lane & 3;
    const int wm   = wid >> 2;
    const int wn   = wid & 3;

    const int bxN = blockIdx.x * 128;
    const int byM = blockIdx.y * 128;

    const int aRow = tid >> 2;
    const int aCol = (tid & 3) << 2;
    const int bRow = tid >> 5;
    const int bCol = (tid & 31) << 2;

    float acc[4][4][4];
#pragma unroll
    for (int i = 0; i < 4; i++)
#pragma unroll
        for (int j = 0; j < 4; j++)
#pragma unroll
            for (int c = 0; c < 4; c++) acc[i][j][c] = 0.f;

#pragma unroll
    for (int i = 0; i < 2; i++) {
        float4 v = *(const float4*)&A[(size_t)(byM + aRow + i * 64) * K + aCol];
        int m = aRow + i * 64;
        sA[0][(aCol + 0) * SAB_STRIDE + m] = f2tf32(v.x);
        sA[0][(aCol + 1) * SAB_STRIDE + m] = f2tf32(v.y);
        sA[0][(aCol + 2) * SAB_STRIDE + m] = f2tf32(v.z);
        sA[0][(aCol + 3) * SAB_STRIDE + m] = f2tf32(v.w);
    }
#pragma unroll
    for (int i = 0; i < 2; i++) {
        float4 v = *(const float4*)&B[(size_t)(bRow + i * 8) * N + bxN + bCol];
        uint4 u = make_uint4(f2tf32(v.x), f2tf32(v.y), f2tf32(v.z), f2tf32(v.w));
        *(uint4*)&sB[0][(bRow + i * 8) * SAB_STRIDE + bCol] = u;
    }
    __syncthreads();

    int buf = 0;
    for (int kt = 0; kt < K; kt += 16) {
        const int nxt = kt + 16;
        float4 pa[2], pb[2];
        if (nxt < K) {
#pragma unroll
            for (int i = 0; i < 2; i++)
                pa[i] = *(const float4*)&A[(size_t)(byM + aRow + i * 64) * K + nxt + aCol];
#pragma unroll
            for (int i = 0; i < 2; i++)
                pb[i] = *(const float4*)&B[(size_t)(nxt + bRow + i * 8) * N + bxN + bCol];
        }

#pragma unroll
        for (int kc = 0; kc < 2; kc++) {
            const int k0 = kc * 8 + t;
            uint32_t afr[4][4], bfr[4][2];
#pragma unroll
            for (int mi = 0; mi < 4; mi++) {
                int mr = wm * 64 + mi * 16 + g;
                afr[mi][0] = sA[buf][k0 * SAB_STRIDE + mr];
                afr[mi][1] = sA[buf][k0 * SAB_STRIDE + mr + 8];
                afr[mi][2] = sA[buf][(k0 + 4) * SAB_STRIDE + mr];
                afr[mi][3] = sA[buf][(k0 + 4) * SAB_STRIDE + mr + 8];
            }
#pragma unroll
            for (int ni = 0; ni < 4; ni++) {
                int nb = wn * 32 + ni * 8 + g;
                bfr[ni][0] = sB[buf][k0 * SAB_STRIDE + nb];
                bfr[ni][1] = sB[buf][(k0 + 4) * SAB_STRIDE + nb];
            }
#pragma unroll
            for (int mi = 0; mi < 4; mi++)
#pragma unroll
                for (int ni = 0; ni < 4; ni++)
                    mma_tf32(acc[mi][ni], afr[mi], bfr[ni]);
        }

        if (nxt < K) {
            const int nb = buf ^ 1;
#pragma unroll
            for (int i = 0; i < 2; i++) {
                int m = aRow + i * 64;
                sA[nb][(aCol + 0) * SAB_STRIDE + m] = f2tf32(pa[i].x);
                sA[nb][(aCol + 1) * SAB_STRIDE + m] = f2tf32(pa[i].y);
                sA[nb][(aCol + 2) * SAB_STRIDE + m] = f2tf32(pa[i].z);
                sA[nb][(aCol + 3) * SAB_STRIDE + m] = f2tf32(pa[i].w);
            }
#pragma unroll
            for (int i = 0; i < 2; i++) {
                uint4 u = make_uint4(f2tf32(pb[i].x), f2tf32(pb[i].y),
                                     f2tf32(pb[i].z), f2tf32(pb[i].w));
                *(uint4*)&sB[nb][(bRow + i * 8) * SAB_STRIDE + bCol] = u;
            }
        }
        __syncthreads();
        buf ^= 1;
    }

#pragma unroll
    for (int mi = 0; mi < 4; mi++) {
#pragma unroll
        for (int ni = 0; ni < 4; ni++) {
            int row = byM + wm * 64 + mi * 16 + g;
            int col = bxN + wn * 32 + ni * 8 + 2 * t;
            *(float2*)&C[(size_t)row * N + col]       = make_float2(acc[mi][ni][0], acc[mi][ni][1]);
            *(float2*)&C[(size_t)(row + 8) * N + col] = make_float2(acc[mi][ni][2], acc[mi][ni][3]);
        }
    }
}

// ---------------------------------------------------------------------------
// RoPE (in-place), unchanged.
// ---------------------------------------------------------------------------
__global__ void rope_kernel(float* __restrict__ X, int nheads, float scale) {
    int idx = blockIdx.x * blockDim.x + threadIdx.x;
    int total = S_LEN * nheads * 64;
    if (idx >= total) return;
    int p    = idx & 63;
    int th   = idx >> 6;
    int head = th % nheads;
    int s    = th / nheads;

    float invf = (float)exp(-(double)p * (1.0 / 64.0) * log(10000.0));
    float ff   = (float)s * invf;
    double cd, sd;
    sincos((double)ff, &sd, &cd);
    float c  = (float)cd;
    float sn = (float)sd;

    size_t base = ((size_t)s * nheads + head) * HDIM;
    float x1 = X[base + p];
    float x2 = X[base + p + 64];
    X[base + p]      = (x1 * c - x2 * sn) * scale;
    X[base + p + 64] = (x2 * c + x1 * sn) * scale;
}

// ---------------------------------------------------------------------------
// Block-sparse flash attention, tensor-core 3xTF32 (fp32-equivalent accuracy).
// Grid: (q_block, head). 256 threads = 8 warps (2 wm x 4 wn).
// Warp tile 64x32, mma.m16n8k8, per-thread acc 4x4x4.
// Smem (floats): sQ[128][132] | sK/P overlay[128][132] | sV[128][136] | red[1024]
// All f32 in smem; hi/lo tf32 fragments built in registers at load.
// Strides chosen conflict-free: 132 -> banks 4g+t (Q/K/P frags), 136 -> 8t+g (V).
// ---------------------------------------------------------------------------
#define SQK_STRIDE 132
#define SV_STRIDE  136
#define ATT_SMEM_FLOATS (16896 * 2 + 17408 + 1024)  // 52224 floats = 208896 B

__global__ __launch_bounds__(256, 1) void attn_mma_kernel(const float* __restrict__ Q,
                                                          const float* __restrict__ K,
                                                          const float* __restrict__ V,
                                                          float* __restrict__ AO) {
    extern __shared__ float sm[];
    float* sQ   = sm;                 // [128][132]
    float* sKP  = sm + 16896;         // K then P (overlay) [128][132]
    float* sV   = sm + 33792;         // [128][136]
    float* redm = sm + 51200;         // [128][4]
    float* reds = sm + 51712;         // [128][4]

    const int iq   = blockIdx.x;
    const int h    = blockIdx.y;
    const int kvh  = h >> 2;          // n_rep = 4
    const int tid  = threadIdx.x;
    const int lane = tid & 31;
    const int wid  = tid >> 5;
    const int g    = lane >> 2;
    const int t    = lane & 3;
    const int wm   = wid >> 2;        // 0..1
    const int wn   = wid & 3;         // 0..3

    // Load Q tile (RoPE'd, pre-scaled)
    for (int idx = tid; idx < 128 * 32; idx += 256) {
        int r = idx >> 5, c4 = (idx & 31) << 2;
        *(float4*)&sQ[r * SQK_STRIDE + c4] =
            *(const float4*)&Q[(size_t)(iq * 128 + r) * (NHEAD * HDIM) + h * HDIM + c4];
    }

    float m_i[8], l_i[8], oacc[4][4][4];
#pragma unroll
    for (int i = 0; i < 8; i++) { m_i[i] = -CUDART_INF_F; l_i[i] = 0.f; }
#pragma unroll
    for (int mi = 0; mi < 4; mi++)
#pragma unroll
        for (int ni = 0; ni < 4; ni++)
#pragma unroll
            for (int cc = 0; cc < 4; cc++) oacc[mi][ni][cc] = 0.f;

    const int jlo = (iq - 7 < 1) ? 1 : (iq - 7);
    const int nbl = (iq == 0) ? 1 : (iq - jlo + 2);

    for (int b = 0; b < nbl; b++) {
        const int j = (b == 0) ? 0 : (jlo + b - 1);

        __syncthreads();  // previous PV reads / P stores done; Q visible
        for (int idx = tid; idx < 128 * 32; idx += 256) {
            int r = idx >> 5, c4 = (idx & 31) << 2;
            size_t goff = (size_t)(j * 128 + r) * (NKVH * HDIM) + kvh * HDIM + c4;
            *(float4*)&sKP[r * SQK_STRIDE + c4] = *(const float4*)&K[goff];
            *(float4*)&sV[r * SV_STRIDE + c4]   = *(const float4*)&V[goff];
        }
        __syncthreads();

        // ---- S = Q @ K^T via 3xTF32 mma ----
        float sreg[4][4][4];
#pragma unroll
        for (int mi = 0; mi < 4; mi++)
#pragma unroll
            for (int ni = 0; ni < 4; ni++)
#pragma unroll
                for (int cc = 0; cc < 4; cc++) sreg[mi][ni][cc] = 0.f;

#pragma unroll 2
        for (int ks = 0; ks < 16; ks++) {
            const int k0 = ks * 8;
            uint32_t ah[4][4], al[4][4], bh[4][2], bl[4][2];
#pragma unroll
            for (int mi = 0; mi < 4; mi++) {
                int mr = wm * 64 + mi * 16 + g;
                split_tf32(sQ[mr * SQK_STRIDE + k0 + t],           ah[mi][0], al[mi][0]);
                split_tf32(sQ[(mr + 8) * SQK_STRIDE + k0 + t],     ah[mi][1], al[mi][1]);
                split_tf32(sQ[mr * SQK_STRIDE + k0 + t + 4],       ah[mi][2], al[mi][2]);
                split_tf32(sQ[(mr + 8) * SQK_STRIDE + k0 + t + 4], ah[mi][3], al[mi][3]);
            }
#pragma unroll
            for (int ni = 0; ni < 4; ni++) {
                int nr = wn * 32 + ni * 8 + g;
                split_tf32(sKP[nr * SQK_STRIDE + k0 + t],     bh[ni][0], bl[ni][0]);
                split_tf32(sKP[nr * SQK_STRIDE + k0 + t + 4], bh[ni][1], bl[ni][1]);
            }
#pragma unroll
            for (int mi = 0; mi < 4; mi++)
#pragma unroll
                for (int ni = 0; ni < 4; ni++) {
                    mma_tf32(sreg[mi][ni], ah[mi], bl[ni]);
                    mma_tf32(sreg[mi][ni], al[mi], bh[ni]);
                    mma_tf32(sreg[mi][ni], ah[mi], bh[ni]);
                }
        }

        // ---- causal mask on the diagonal block ----
        if (j == iq) {
#pragma unroll
            for (int mi = 0; mi < 4; mi++)
#pragma unroll
                for (int ni = 0; ni < 4; ni++)
#pragma unroll
                    for (int cc = 0; cc < 4; cc++) {
                        int row = wm * 64 + mi * 16 + g + ((cc >> 1) << 3);
                        int col = wn * 32 + ni * 8 + 2 * t + (cc & 1);
                        if (col > row) sreg[mi][ni][cc] = -CUDART_INF_F;
                    }
        }

        // ---- row max: local -> shfl over t -> smem over wn ----
        float lmax[4][2];
#pragma unroll
        for (int mi = 0; mi < 4; mi++)
#pragma unroll
            for (int e = 0; e < 2; e++) {
                float m = sreg[mi][0][2 * e];
#pragma unroll
                for (int ni = 0; ni < 4; ni++) {
                    m = fmaxf(m, sreg[mi][ni][2 * e]);
                    m = fmaxf(m, sreg[mi][ni][2 * e + 1]);
                }
                m = fmaxf(m, __shfl_xor_sync(0xffffffffu, m, 1));
                m = fmaxf(m, __shfl_xor_sync(0xffffffffu, m, 2));
                lmax[mi][e] = m;
            }
        if (t == 0) {
#pragma unroll
            for (int mi = 0; mi < 4; mi++)
#pragma unroll
                for (int e = 0; e < 2; e++)
                    redm[(wm * 64 + mi * 16 + g + 8 * e) * 4 + wn] = lmax[mi][e];
        }
        __syncthreads();  // redm ready; all S done (K smem dead)

        float mnew[4][2], scl[4][2];
#pragma unroll
        for (int mi = 0; mi < 4; mi++)
#pragma unroll
            for (int e = 0; e < 2; e++) {
                int row = wm * 64 + mi * 16 + g + 8 * e;
                float m = m_i[mi * 2 + e];
                m = fmaxf(m, redm[row * 4 + 0]);
                m = fmaxf(m, redm[row * 4 + 1]);
                m = fmaxf(m, redm[row * 4 + 2]);
                m = fmaxf(m, redm[row * 4 + 3]);
                mnew[mi][e] = m;
                scl[mi][e]  = expf(m_i[mi * 2 + e] - m);
                m_i[mi * 2 + e] = m;
            }

        // ---- P = exp(S - mnew); rescale O; store P (f32) over K smem ----
        float lsum[4][2] = {{0.f, 0.f}, {0.f, 0.f}, {0.f, 0.f}, {0.f, 0.f}};
#pragma unroll
        for (int mi = 0; mi < 4; mi++)
#pragma unroll
            for (int ni = 0; ni < 4; ni++) {
#pragma unroll
                for (int cc = 0; cc < 4; cc++) {
                    int e = cc >> 1;
                    float p = expf(sreg[mi][ni][cc] - mnew[mi][e]);
                    sreg[mi][ni][cc] = p;
                    lsum[mi][e] += p;
                    oacc[mi][ni][cc] *= scl[mi][e];
                }
                int row0 = wm * 64 + mi * 16 + g;
                int col  = wn * 32 + ni * 8 + 2 * t;
                *(float2*)&sKP[row0 * SQK_STRIDE + col] =
                    make_float2(sreg[mi][ni][0], sreg[mi][ni][1]);
                *(float2*)&sKP[(row0 + 8) * SQK_STRIDE + col] =
                    make_float2(sreg[mi][ni][2], sreg[mi][ni][3]);
            }
#pragma unroll
        for (int mi = 0; mi < 4; mi++)
#pragma unroll
            for (int e = 0; e < 2; e++) {
                float s = lsum[mi][e];
                s += __shfl_xor_sync(0xffffffffu, s, 1);
                s += __shfl_xor_sync(0xffffffffu, s, 2);
                lsum[mi][e] = s;
            }
        if (t == 0) {
#pragma unroll
            for (int mi = 0; mi < 4; mi++)
#pragma unroll
                for (int e = 0; e < 2; e++)
                    reds[(wm * 64 + mi * 16 + g + 8 * e) * 4 + wn] = lsum[mi][e];
        }
        __syncthreads();  // P + reds visible

#pragma unroll
        for (int mi = 0; mi < 4; mi++)
#pragma unroll
            for (int e = 0; e < 2; e++) {
                int row = wm * 64 + mi * 16 + g + 8 * e;
                float rs = reds[row * 4 + 0] + reds[row * 4 + 1] +
                           reds[row * 4 + 2] + reds[row * 4 + 3];
                l_i[mi * 2 + e] = l_i[mi * 2 + e] * scl[mi][e] + rs;
            }

        // ---- O += P @ V via 3xTF32 mma (A = P from smem, B = V natural) ----
#pragma unroll 2
        for (int ks = 0; ks < 16; ks++) {
            const int k0 = ks * 8;
            uint32_t ah[4][4], al[4][4], bh[4][2], bl[4][2];
#pragma unroll
            for (int mi = 0; mi < 4; mi++) {
                int mr = wm * 64 + mi * 16 + g;
                split_tf32(sKP[mr * SQK_STRIDE + k0 + t],           ah[mi][0], al[mi][0]);
                split_tf32(sKP[(mr + 8) * SQK_STRIDE + k0 + t],     ah[mi][1], al[mi][1]);
                split_tf32(sKP[mr * SQK_STRIDE + k0 + t + 4],       ah[mi][2], al[mi][2]);
                split_tf32(sKP[(mr + 8) * SQK_STRIDE + k0 + t + 4], ah[mi][3], al[mi][3]);
            }
#pragma unroll
            for (int ni = 0; ni < 4; ni++) {
                int nr = wn * 32 + ni * 8 + g;
                split_tf32(sV[(k0 + t) * SV_STRIDE + nr],     bh[ni][0], bl[ni][0]);
                split_tf32(sV[(k0 + t + 4) * SV_STRIDE + nr], bh[ni][1], bl[ni][1]);
            }
#pragma unroll
            for (int mi = 0; mi < 4; mi++)
#pragma unroll
                for (int ni = 0; ni < 4; ni++) {
                    mma_tf32(oacc[mi][ni], ah[mi], bl[ni]);
                    mma_tf32(oacc[mi][ni], al[mi], bh[ni]);
                    mma_tf32(oacc[mi][ni], ah[mi], bh[ni]);
                }
        }
    }

    // ---- epilogue: O / l ----
#pragma unroll
    for (int mi = 0; mi < 4; mi++) {
        float inv0 = 1.0f / l_i[mi * 2 + 0];
        float inv1 = 1.0f / l_i[mi * 2 + 1];
#pragma unroll
        for (int ni = 0; ni < 4; ni++) {
            int row0 = wm * 64 + mi * 16 + g;
            int col  = wn * 32 + ni * 8 + 2 * t;
            size_t off = (size_t)(iq * 128 + row0) * (NHEAD * HDIM) + h * HDIM + col;
            *(float2*)&AO[off] =
                make_float2(oacc[mi][ni][0] * inv0, oacc[mi][ni][1] * inv0);
            *(float2*)&AO[off + (size_t)8 * NHEAD * HDIM] =
                make_float2(oacc[mi][ni][2] * inv1, oacc[mi][ni][3] * inv1);
        }
    }
}

// ---------------------------------------------------------------------------
// kernel_launch
// ---------------------------------------------------------------------------
extern "C" void kernel_launch(void* const* d_in, const int* in_sizes, int n_in,
                              void* d_out, int out_size) {
    const float* hs = (const float*)d_in[0];
    const float* wq = (const float*)d_in[1];
    const float* wk = (const float*)d_in[2];
    const float* wv = (const float*)d_in[3];
    const float* wo = (const float*)d_in[4];
    float* out = (float*)d_out;

    float *q, *k, *v, *ao;
    cudaGetSymbolAddress((void**)&q,  g_q);
    cudaGetSymbolAddress((void**)&k,  g_k);
    cudaGetSymbolAddress((void**)&v,  g_v);
    cudaGetSymbolAddress((void**)&ao, g_ao);

    const int att_smem = ATT_SMEM_FLOATS * (int)sizeof(float);  // 208896 B
    cudaFuncSetAttribute(attn_mma_kernel, cudaFuncAttributeMaxDynamicSharedMemorySize, att_smem);

    dim3 blk(256);
    // QKV projections (tf32 tensor cores)
    tgemm_kernel<<<dim3(32, 32), blk>>>(hs, wq, q, S_LEN, NHEAD * HDIM, HIDD);
    tgemm_kernel<<<dim3(8, 32),  blk>>>(hs, wk, k, S_LEN, NKVH * HDIM, HIDD);
    tgemm_kernel<<<dim3(8, 32),  blk>>>(hs, wv, v, S_LEN, NKVH * HDIM, HIDD);
    // RoPE (Q pre-scaled by 1/sqrt(128))
    rope_kernel<<<(S_LEN * NHEAD * 64 + 255) / 256, 256>>>(q, NHEAD, 0.08838834764831845f);
    rope_kernel<<<(S_LEN * NKVH * 64 + 255) / 256, 256>>>(k, NKVH, 1.0f);
    // Block-sparse flash attention (3xTF32 tensor cores, fp32-equivalent)
    attn_mma_kernel<<<dim3(NBLK, NHEAD), blk, att_smem>>>(q, k, v, ao);
    // Output projection (tf32 tensor cores)
    tgemm_kernel<<<dim3(32, 32), blk>>>(ao, wo, out, S_LEN, HIDD, NHEAD * HDIM);
}